// round 15
// baseline (speedup 1.0000x reference)
#include <cuda_runtime.h>
#include <cuda_bf16.h>
#include <math.h>
#include <stdint.h>

#define L 256
#define CH 32
#define DEPTH 4
#define PLANE (L*L)
#define BUF_ELEMS (32u*CH*PLANE)

__device__ float g_bufA[BUF_ELEMS];
__device__ float g_bufB[BUF_ELEMS];

// ---------------- helpers ----------------

__device__ __forceinline__ uint32_t smem_u32(const void* p) {
    uint32_t a;
    asm("{ .reg .u64 t; cvta.to.shared.u64 t, %1; cvt.u32.u64 %0, t; }" : "=r"(a) : "l"(p));
    return a;
}

__device__ __forceinline__ float gelu_f(float v) {
    return 0.5f * v * (1.0f + erff(v * 0.7071067811865476f));
}

__device__ __forceinline__ void ldm_x4(uint32_t* r, uint32_t addr) {
    asm volatile("ldmatrix.sync.aligned.m8n8.x4.shared.b16 {%0,%1,%2,%3}, [%4];"
        : "=r"(r[0]), "=r"(r[1]), "=r"(r[2]), "=r"(r[3]) : "r"(addr));
}

__device__ __forceinline__ void mma_bf16(float* d, const uint32_t* a, const uint32_t* b) {
    asm volatile("mma.sync.aligned.m16n8k16.row.col.f32.bf16.bf16.f32 "
        "{%0,%1,%2,%3}, {%4,%5,%6,%7}, {%8,%9}, {%0,%1,%2,%3};"
        : "+f"(d[0]), "+f"(d[1]), "+f"(d[2]), "+f"(d[3])
        : "r"(a[0]), "r"(a[1]), "r"(a[2]), "r"(a[3]), "r"(b[0]), "r"(b[1]));
}

// ---------------- k_mid_mma: implicit-conv tensor-core middle layer ----------------
// (unchanged from R13 — proven 324 us)

#define CPITCH 80
#define RPITCH 1440
#define BPITCH 208
#define H0_OFF 0
#define H1_OFF 25920
#define B0_OFF 51840
#define B1_OFF 58496
#define BIAS_OFF 65152
#define SMEM_TOTAL 65344

__global__ void __launch_bounds__(256, 3)
k_mid_mma(const float* __restrict__ wa_g, const float* __restrict__ wb_g,
          const float* __restrict__ wc_g, const float* __restrict__ bias_g,
          int layer, int dir)
{
    extern __shared__ char smc[];
    float* bias_s = (float*)(smc + BIAS_OFF);
    uint32_t smem_base = smem_u32(smc);

    const float* src = dir ? g_bufB : g_bufA;
    float*       dst = dir ? g_bufA : g_bufB;

    int tid = threadIdx.x;
    int wid = tid >> 5;
    int lane = tid & 31;
    int tx0 = blockIdx.x * 16, ty0 = blockIdx.y * 16, bb = blockIdx.z;

    {
        const float* wc = wc_g + layer * 1024;
        const float* wb = wb_g + layer * 1024;
        const float* wa = wa_g + layer * 1024;
        char* B0c = smc + B0_OFF;
        char* B1c = smc + B1_OFF;
        for (int idx = tid; idx < 96 * 32; idx += 256) {
            int o = idx & 31, kk = idx >> 5;
            const float* ws = (kk < 32) ? wc : (kk < 64) ? wb : wa;
            float v = ws[(o << 5) + (kk & 31)];
            __nv_bfloat16 h0 = __float2bfloat16(v);
            float r = v - __bfloat162float(h0);
            *reinterpret_cast<__nv_bfloat16*>(B0c + o * BPITCH + kk * 2) = h0;
            *reinterpret_cast<__nv_bfloat16*>(B1c + o * BPITCH + kk * 2) = __float2bfloat16(r);
        }
        if (tid < 32) bias_s[tid] = bias_g[layer * 32 + tid];
    }

    {
        const float* inb = src + ((bb * CH) << 16);
        for (int t = tid; t < 324; t += 256) {
            int r = t / 18, c = t - r * 18;
            int gy = (ty0 + r + 255) & 255;
            int gx = (tx0 + c + 255) & 255;
            const float* g = inb + (gy << 8) + gx;
            char* h0 = smc + H0_OFF + r * RPITCH + c * CPITCH;
            char* h1 = smc + H1_OFF + r * RPITCH + c * CPITCH;
            #pragma unroll
            for (int ch2 = 0; ch2 < 16; ch2++) {
                float v0 = g[(ch2 * 2) << 16];
                float v1 = g[(ch2 * 2 + 1) << 16];
                __nv_bfloat16 a0 = __float2bfloat16(v0);
                __nv_bfloat16 a1 = __float2bfloat16(v1);
                __nv_bfloat162 hi; hi.x = a0; hi.y = a1;
                __nv_bfloat162 lo;
                lo.x = __float2bfloat16(v0 - __bfloat162float(a0));
                lo.y = __float2bfloat16(v1 - __bfloat162float(a1));
                *reinterpret_cast<__nv_bfloat162*>(h0 + ch2 * 4) = hi;
                *reinterpret_cast<__nv_bfloat162*>(h1 + ch2 * 4) = lo;
            }
        }
    }
    __syncthreads();

    float acc[2][4][4] = {};
    int pr0 = wid << 1;
    uint32_t laneA = (uint32_t)((lane & 15) * CPITCH + (lane >> 4) * 16);
    uint32_t aB  = smem_base + B0_OFF
                 + (uint32_t)(((((lane >> 4) << 3) + (lane & 7)) * BPITCH) + ((lane >> 3) & 1) * 16);
    uint32_t aBl = aB + (B1_OFF - B0_OFF);

    #pragma unroll
    for (int kc = 0; kc < 2; kc++) {
        uint32_t bhS[8], blS[8];
        uint32_t bh1[8], bl1[8];

        uint32_t kb0 = (uint32_t)(kc * 32);
        ldm_x4(bhS,     aB  + kb0);
        ldm_x4(bhS + 4, aB  + kb0 + 16 * BPITCH);
        ldm_x4(blS,     aBl + kb0);
        ldm_x4(blS + 4, aBl + kb0 + 16 * BPITCH);
        uint32_t kb1 = (uint32_t)(64 + kc * 32);
        ldm_x4(bh1,     aB  + kb1);
        ldm_x4(bh1 + 4, aB  + kb1 + 16 * BPITCH);
        ldm_x4(bl1,     aBl + kb1);
        ldm_x4(bl1 + 4, aBl + kb1 + 16 * BPITCH);

        auto do3 = [&](int t, bool useS, const uint32_t* ah, const uint32_t* al) {
            const uint32_t* bh = useS ? bhS : bh1;
            const uint32_t* bl = useS ? blS : bl1;
            #pragma unroll
            for (int nt = 0; nt < 4; nt++) mma_bf16(acc[t][nt], ah, &bh[nt * 2]);
            #pragma unroll
            for (int nt = 0; nt < 4; nt++) mma_bf16(acc[t][nt], al, &bh[nt * 2]);
            #pragma unroll
            for (int nt = 0; nt < 4; nt++) mma_bf16(acc[t][nt], ah, &bl[nt * 2]);
        };

        #pragma unroll
        for (int R = 0; R < 4; R++) {
            uint32_t a0 = smem_base + H0_OFF
                        + (uint32_t)((pr0 + R) * RPITCH + 1 * CPITCH + kc * 32) + laneA;
            uint32_t ah[4], al[4];
            ldm_x4(ah, a0);
            ldm_x4(al, a0 + (H1_OFF - H0_OFF));
            if (R <= 2) do3(0, (R == 1), ah, al);
            if (R >= 1) do3(1, (R == 2), ah, al);
        }

        uint32_t kb2 = (uint32_t)(128 + kc * 32);
        ldm_x4(bhS,     aB  + kb2);
        ldm_x4(bhS + 4, aB  + kb2 + 16 * BPITCH);
        ldm_x4(blS,     aBl + kb2);
        ldm_x4(blS + 4, aBl + kb2 + 16 * BPITCH);

        #pragma unroll
        for (int dd = 0; dd < 2; dd++) {
            const int d = dd * 2;
            #pragma unroll
            for (int R = 0; R < 4; R++) {
                uint32_t a0 = smem_base + H0_OFF
                            + (uint32_t)((pr0 + R) * RPITCH + d * CPITCH + kc * 32) + laneA;
                uint32_t ah[4], al[4];
                ldm_x4(ah, a0);
                ldm_x4(al, a0 + (H1_OFF - H0_OFF));
                if (R <= 2) do3(0, (R != 1), ah, al);
                if (R >= 1) do3(1, (R != 2), ah, al);
            }
        }
    }

    {
        int r = lane >> 2, c2 = (lane & 3) << 1;
        #pragma unroll
        for (int nt = 0; nt < 4; nt++) {
            int o = (nt << 3) + c2;
            float b0 = bias_s[o], b1 = bias_s[o + 1];
            #pragma unroll
            for (int t = 0; t < 2; t++) {
                float* bp = dst + ((uint32_t)(bb * CH + o) << 16)
                          + ((uint32_t)(ty0 + pr0 + t) << 8) + tx0;
                bp[r]             = gelu_f(acc[t][nt][0] + b0);
                bp[65536 + r]     = gelu_f(acc[t][nt][1] + b1);
                bp[r + 8]         = gelu_f(acc[t][nt][2] + b0);
                bp[65536 + r + 8] = gelu_f(acc[t][nt][3] + b1);
            }
        }
    }
}

// ---------------- kernel 1: first layer (1 -> 32 ch) + gelu, 1024-thr parallel ----------------
// Tile 32x8 px. Phase 1: stage x halo + compute features once. Phase 2:
// thread = (channel-octet, pixel); warp = 32 consecutive px -> coalesced STG.
__global__ void __launch_bounds__(1024, 1)
k_first(const float* __restrict__ x,
        const float* __restrict__ ci, const float* __restrict__ bi,
        const float* __restrict__ ai, const float* __restrict__ bias_i,
        float sign)
{
    __shared__ float w[128];
    __shared__ float xh[340];          // halo 10 rows x 34 cols
    __shared__ float fC[256], fN[256], fD[256];

    int tid = threadIdx.x;
    int tx0 = blockIdx.x * 32, ty0 = blockIdx.y * 8, b = blockIdx.z;

    if (tid < 128) {
        w[tid] = (tid < 32) ? ci[tid]
               : (tid < 64) ? bi[tid - 32]
               : (tid < 96) ? ai[tid - 64]
                            : bias_i[tid - 96];
    }
    if (tid < 340) {
        int r = tid / 34, c = tid - r * 34;
        int gy = (ty0 + r + 255) & 255;
        int gx = (tx0 + c + 255) & 255;
        xh[tid] = sign * x[(b << 16) + (gy << 8) + gx];
    }
    __syncthreads();

    if (tid < 256) {
        int r = tid >> 5, c = tid & 31;
        int base = (r + 1) * 34 + c + 1;
        fC[tid] = xh[base];
        fN[tid] = xh[base - 34] + xh[base + 34] + xh[base - 1] + xh[base + 1];
        fD[tid] = xh[base - 35] + xh[base + 35] + xh[base - 33] + xh[base + 33];
    }
    __syncthreads();

    int px = tid & 255;
    int q  = tid >> 8;                 // channel octet
    float ctr = fC[px], nb = fN[px], dg = fD[px];
    int gy = ty0 + (px >> 5), gx = tx0 + (px & 31);
    float* outp = g_bufA + ((b * CH) << 16) + (gy << 8) + gx;
    #pragma unroll
    for (int j = 0; j < 8; j++) {
        int o = q * 8 + j;
        float v = w[o] * ctr + w[32 + o] * nb + w[64 + o] * dg + w[96 + o];
        outp[o << 16] = gelu_f(v);
    }
}

// ---------------- kernel 3: last layer (32 -> 1 ch), 1024-thr parallel ----------------
// 4 threads per px x 8 channels each; smem partial reduction.
#define HS1 (32*340)
__global__ void __launch_bounds__(1024, 1)
k_last(const float* __restrict__ co, const float* __restrict__ bo,
       const float* __restrict__ ao, float* __restrict__ out, int mode)
{
    __shared__ float Hs[HS1];          // [ch][340]
    __shared__ float ws[96];
    __shared__ float partial[1024];

    int tid = threadIdx.x;
    int tx0 = blockIdx.x * 32, ty0 = blockIdx.y * 8, b = blockIdx.z;
    const float* inb = g_bufA + ((b * CH) << 16);

    for (int t = tid; t < HS1; t += 1024) {
        int i   = t / 340;
        int rem = t - i * 340;
        int r   = rem / 34;
        int cc  = rem - r * 34;
        int gy  = (ty0 + r + 255) & 255;
        int gx  = (tx0 + cc + 255) & 255;
        Hs[t] = inb[(i << 16) + (gy << 8) + gx];
    }
    if (tid < 96) {
        ws[tid] = (tid < 32) ? co[tid] : (tid < 64) ? bo[tid - 32] : ao[tid - 64];
    }
    __syncthreads();

    {
        int px = tid & 255;
        int q  = tid >> 8;
        int base = ((px >> 5) + 1) * 34 + (px & 31) + 1;
        float acc = 0.f;
        #pragma unroll
        for (int j = 0; j < 8; j++) {
            int i = q * 8 + j;
            const float* h = Hs + i * 340;
            float ctr = h[base];
            float nb  = h[base - 34] + h[base + 34] + h[base - 1]  + h[base + 1];
            float dg  = h[base - 35] + h[base + 35] + h[base - 33] + h[base + 33];
            acc += ws[i] * ctr + ws[32 + i] * nb + ws[64 + i] * dg;
        }
        partial[(q << 8) + px] = acc;
    }
    __syncthreads();

    if (tid < 256) {
        float acc = partial[tid] + partial[256 + tid] + partial[512 + tid] + partial[768 + tid];
        int gy = ty0 + (tid >> 5), gx = tx0 + (tid & 31);
        int oidx = (b << 16) + (gy << 8) + gx;
        if (mode == 0) out[oidx] = 0.5f * acc;
        else           out[oidx] -= 0.5f * acc;
    }
}

// ---------------- launcher ----------------

extern "C" void kernel_launch(void* const* d_in, const int* in_sizes, int n_in,
                              void* d_out, int out_size)
{
    const float* x      = (const float*)d_in[0];
    const float* ai     = (const float*)d_in[1];
    const float* ao     = (const float*)d_in[2];
    const float* a      = (const float*)d_in[3];
    const float* bi     = (const float*)d_in[4];
    const float* bo     = (const float*)d_in[5];
    const float* b      = (const float*)d_in[6];
    const float* ci     = (const float*)d_in[7];
    const float* co     = (const float*)d_in[8];
    const float* c      = (const float*)d_in[9];
    const float* bias_i = (const float*)d_in[10];
    const float* bias   = (const float*)d_in[11];
    float* out = (float*)d_out;

    cudaFuncSetAttribute(k_mid_mma, cudaFuncAttributeMaxDynamicSharedMemorySize, SMEM_TOTAL);

    dim3 gridM(16, 16, 32);
    dim3 gridS(8, 32, 32);

    for (int s = 0; s < 2; s++) {
        float sign = s ? -1.f : 1.f;
        k_first<<<gridS, 1024>>>(x, ci, bi, ai, bias_i, sign);
        int dir = 0;
        for (int k = 0; k < DEPTH; k++) {
            k_mid_mma<<<gridM, 256, SMEM_TOTAL>>>(a, b, c, bias, k, dir);
            dir ^= 1;
        }
        k_last<<<gridS, 1024>>>(co, bo, ao, out, s);
    }
}

// round 17
// speedup vs baseline: 1.3613x; 1.3613x over previous
#include <cuda_runtime.h>
#include <cuda_bf16.h>
#include <math.h>
#include <stdint.h>

#define L 256
#define CH 32
#define DEPTH 4
#define PLANE (L*L)
// 64 "batches" = 32 real batches x 2 signs. 512 MB per buffer.
#define BUF_ELEMS (64u*CH*PLANE)

__device__ float g_bufA[BUF_ELEMS];
__device__ float g_bufB[BUF_ELEMS];
// Pre-split weights: [layer][plane hi/lo][32 o x 104 halves (208 B pitch)]
__device__ __nv_bfloat16 g_wsplit[DEPTH][2][32 * 104];

// ---------------- helpers ----------------

__device__ __forceinline__ uint32_t smem_u32(const void* p) {
    uint32_t a;
    asm("{ .reg .u64 t; cvta.to.shared.u64 t, %1; cvt.u32.u64 %0, t; }" : "=r"(a) : "l"(p));
    return a;
}

__device__ __forceinline__ float gelu_f(float v) {
    return 0.5f * v * (1.0f + erff(v * 0.7071067811865476f));
}

__device__ __forceinline__ void ldm_x4(uint32_t* r, uint32_t addr) {
    asm volatile("ldmatrix.sync.aligned.m8n8.x4.shared.b16 {%0,%1,%2,%3}, [%4];"
        : "=r"(r[0]), "=r"(r[1]), "=r"(r[2]), "=r"(r[3]) : "r"(addr));
}

__device__ __forceinline__ void mma_bf16(float* d, const uint32_t* a, const uint32_t* b) {
    asm volatile("mma.sync.aligned.m16n8k16.row.col.f32.bf16.bf16.f32 "
        "{%0,%1,%2,%3}, {%4,%5,%6,%7}, {%8,%9}, {%0,%1,%2,%3};"
        : "+f"(d[0]), "+f"(d[1]), "+f"(d[2]), "+f"(d[3])
        : "r"(a[0]), "r"(a[1]), "r"(a[2]), "r"(a[3]), "r"(b[0]), "r"(b[1]));
}

// ---------------- k_wprep: split weights once, in smem layout ----------------
// grid 8: blockIdx.x = layer*2 + plane. 256 threads.
__global__ void k_wprep(const float* __restrict__ wa_g, const float* __restrict__ wb_g,
                        const float* __restrict__ wc_g)
{
    int layer = blockIdx.x >> 1;
    int plane = blockIdx.x & 1;
    const float* wc = wc_g + layer * 1024;
    const float* wb = wb_g + layer * 1024;
    const float* wa = wa_g + layer * 1024;
    __nv_bfloat16* dstp = g_wsplit[layer][plane];
    for (int idx = threadIdx.x; idx < 96 * 32; idx += 256) {
        int o = idx & 31, kk = idx >> 5;
        const float* ws = (kk < 32) ? wc : (kk < 64) ? wb : wa;
        float v = ws[(o << 5) + (kk & 31)];
        __nv_bfloat16 h0 = __float2bfloat16(v);
        dstp[o * 104 + kk] = plane ? __float2bfloat16(v - __bfloat162float(h0)) : h0;
    }
}

// ---------------- k_mid_mma: implicit-conv tensor-core middle layer ----------------
// (R13 mainloop, weights via g_wsplit memcpy, bb in [0,64))

#define CPITCH 80
#define RPITCH 1440
#define BPITCH 208
#define H0_OFF 0
#define H1_OFF 25920
#define B0_OFF 51840
#define B1_OFF 58496
#define BIAS_OFF 65152
#define SMEM_TOTAL 65344

__global__ void __launch_bounds__(256, 3)
k_mid_mma(const float* __restrict__ bias_g, int layer, int dir)
{
    extern __shared__ char smc[];
    float* bias_s = (float*)(smc + BIAS_OFF);
    uint32_t smem_base = smem_u32(smc);

    const float* src = dir ? g_bufB : g_bufA;
    float*       dst = dir ? g_bufA : g_bufB;

    int tid = threadIdx.x;
    int wid = tid >> 5;
    int lane = tid & 31;
    int tx0 = blockIdx.x * 16, ty0 = blockIdx.y * 16, bb = blockIdx.z;

    // -------- weights: straight memcpy of pre-split planes --------
    {
        const uint4* w0 = reinterpret_cast<const uint4*>(g_wsplit[layer][0]);
        const uint4* w1 = reinterpret_cast<const uint4*>(g_wsplit[layer][1]);
        uint4* b0 = reinterpret_cast<uint4*>(smc + B0_OFF);
        uint4* b1 = reinterpret_cast<uint4*>(smc + B1_OFF);
        for (int t = tid; t < 416; t += 256) {     // 32*208/16 = 416 uint4 per plane
            b0[t] = w0[t];
            b1[t] = w1[t];
        }
        if (tid < 32) bias_s[tid] = bias_g[layer * 32 + tid];
    }

    // -------- halo load + split-bf16 store, channel-contiguous --------
    {
        const float* inb = src + (((uint32_t)bb * CH) << 16);
        for (int t = tid; t < 324; t += 256) {
            int r = t / 18, c = t - r * 18;
            int gy = (ty0 + r + 255) & 255;
            int gx = (tx0 + c + 255) & 255;
            const float* g = inb + (gy << 8) + gx;
            char* h0 = smc + H0_OFF + r * RPITCH + c * CPITCH;
            char* h1 = smc + H1_OFF + r * RPITCH + c * CPITCH;
            #pragma unroll
            for (int ch2 = 0; ch2 < 16; ch2++) {
                float v0 = g[(ch2 * 2) << 16];
                float v1 = g[(ch2 * 2 + 1) << 16];
                __nv_bfloat16 a0 = __float2bfloat16(v0);
                __nv_bfloat16 a1 = __float2bfloat16(v1);
                __nv_bfloat162 hi; hi.x = a0; hi.y = a1;
                __nv_bfloat162 lo;
                lo.x = __float2bfloat16(v0 - __bfloat162float(a0));
                lo.y = __float2bfloat16(v1 - __bfloat162float(a1));
                *reinterpret_cast<__nv_bfloat162*>(h0 + ch2 * 4) = hi;
                *reinterpret_cast<__nv_bfloat162*>(h1 + ch2 * 4) = lo;
            }
        }
    }
    __syncthreads();

    // -------- MMA mainloop (phase-pair, shared A fragments) --------
    float acc[2][4][4] = {};
    int pr0 = wid << 1;
    uint32_t laneA = (uint32_t)((lane & 15) * CPITCH + (lane >> 4) * 16);
    uint32_t aB  = smem_base + B0_OFF
                 + (uint32_t)(((((lane >> 4) << 3) + (lane & 7)) * BPITCH) + ((lane >> 3) & 1) * 16);
    uint32_t aBl = aB + (B1_OFF - B0_OFF);

    #pragma unroll
    for (int kc = 0; kc < 2; kc++) {
        uint32_t bhS[8], blS[8];
        uint32_t bh1[8], bl1[8];

        uint32_t kb0 = (uint32_t)(kc * 32);
        ldm_x4(bhS,     aB  + kb0);
        ldm_x4(bhS + 4, aB  + kb0 + 16 * BPITCH);
        ldm_x4(blS,     aBl + kb0);
        ldm_x4(blS + 4, aBl + kb0 + 16 * BPITCH);
        uint32_t kb1 = (uint32_t)(64 + kc * 32);
        ldm_x4(bh1,     aB  + kb1);
        ldm_x4(bh1 + 4, aB  + kb1 + 16 * BPITCH);
        ldm_x4(bl1,     aBl + kb1);
        ldm_x4(bl1 + 4, aBl + kb1 + 16 * BPITCH);

        auto do3 = [&](int t, bool useS, const uint32_t* ah, const uint32_t* al) {
            const uint32_t* bh = useS ? bhS : bh1;
            const uint32_t* bl = useS ? blS : bl1;
            #pragma unroll
            for (int nt = 0; nt < 4; nt++) mma_bf16(acc[t][nt], ah, &bh[nt * 2]);
            #pragma unroll
            for (int nt = 0; nt < 4; nt++) mma_bf16(acc[t][nt], al, &bh[nt * 2]);
            #pragma unroll
            for (int nt = 0; nt < 4; nt++) mma_bf16(acc[t][nt], ah, &bl[nt * 2]);
        };

        #pragma unroll
        for (int R = 0; R < 4; R++) {
            uint32_t a0 = smem_base + H0_OFF
                        + (uint32_t)((pr0 + R) * RPITCH + 1 * CPITCH + kc * 32) + laneA;
            uint32_t ah[4], al[4];
            ldm_x4(ah, a0);
            ldm_x4(al, a0 + (H1_OFF - H0_OFF));
            if (R <= 2) do3(0, (R == 1), ah, al);
            if (R >= 1) do3(1, (R == 2), ah, al);
        }

        uint32_t kb2 = (uint32_t)(128 + kc * 32);
        ldm_x4(bhS,     aB  + kb2);
        ldm_x4(bhS + 4, aB  + kb2 + 16 * BPITCH);
        ldm_x4(blS,     aBl + kb2);
        ldm_x4(blS + 4, aBl + kb2 + 16 * BPITCH);

        #pragma unroll
        for (int dd = 0; dd < 2; dd++) {
            const int d = dd * 2;
            #pragma unroll
            for (int R = 0; R < 4; R++) {
                uint32_t a0 = smem_base + H0_OFF
                            + (uint32_t)((pr0 + R) * RPITCH + d * CPITCH + kc * 32) + laneA;
                uint32_t ah[4], al[4];
                ldm_x4(ah, a0);
                ldm_x4(al, a0 + (H1_OFF - H0_OFF));
                if (R <= 2) do3(0, (R != 1), ah, al);
                if (R >= 1) do3(1, (R != 2), ah, al);
            }
        }
    }

    // -------- epilogue: bias + gelu, direct sector-aligned STG --------
    {
        int r = lane >> 2, c2 = (lane & 3) << 1;
        #pragma unroll
        for (int nt = 0; nt < 4; nt++) {
            int o = (nt << 3) + c2;
            float b0 = bias_s[o], b1 = bias_s[o + 1];
            #pragma unroll
            for (int t = 0; t < 2; t++) {
                float* bp = dst + (((uint32_t)bb * CH + o) << 16)
                          + ((uint32_t)(ty0 + pr0 + t) << 8) + tx0;
                bp[r]             = gelu_f(acc[t][nt][0] + b0);
                bp[65536 + r]     = gelu_f(acc[t][nt][1] + b1);
                bp[r + 8]         = gelu_f(acc[t][nt][2] + b0);
                bp[65536 + r + 8] = gelu_f(acc[t][nt][3] + b1);
            }
        }
    }
}

// ---------------- kernel 1: first layer (1 -> 32 ch) + gelu (R13 form, sign-fused) ----------------
// grid (8, 32, 64): z = sign*32 + batch.
__global__ void k_first(const float* __restrict__ x,
                        const float* __restrict__ ci, const float* __restrict__ bi,
                        const float* __restrict__ ai, const float* __restrict__ bias_i)
{
    __shared__ float w[128];
    int tid = threadIdx.y * 32 + threadIdx.x;
    if (tid < 128) {
        w[tid] = (tid < 32) ? ci[tid]
               : (tid < 64) ? bi[tid - 32]
               : (tid < 96) ? ai[tid - 64]
                            : bias_i[tid - 96];
    }
    __syncthreads();

    int gx = blockIdx.x * 32 + threadIdx.x;
    int gy = blockIdx.y * 8  + threadIdx.y;
    int z  = blockIdx.z;
    int b  = z & 31;
    float sign = (z & 32) ? -1.f : 1.f;

    const float* xb = x + (b << 16);
    int xm = (gx + 255) & 255, xq = (gx + 1) & 255;
    int ym = (gy + 255) & 255, yq = (gy + 1) & 255;

    float ctr = xb[(gy << 8) + gx];
    float nb  = xb[(ym << 8) + gx] + xb[(yq << 8) + gx]
              + xb[(gy << 8) + xm] + xb[(gy << 8) + xq];
    float dg  = xb[(ym << 8) + xm] + xb[(ym << 8) + xq]
              + xb[(yq << 8) + xm] + xb[(yq << 8) + xq];
    ctr *= sign; nb *= sign; dg *= sign;

    float* outp = g_bufA + (((uint32_t)z * CH) << 16) + (gy << 8) + gx;
    #pragma unroll
    for (int o = 0; o < 32; o++) {
        float v = w[o] * ctr + w[32 + o] * nb + w[64 + o] * dg + w[96 + o];
        outp[(uint32_t)o << 16] = gelu_f(v);
    }
}

// ---------------- kernel 3: last layer (32 -> 1 ch), both signs in one pass ----------------
#define HS1 (32*10*34)
__global__ void k_last(const float* __restrict__ co, const float* __restrict__ bo,
                       const float* __restrict__ ao, float* __restrict__ out)
{
    __shared__ float Hs[HS1];
    __shared__ float ws[96];
    int tx = threadIdx.x, ty = threadIdx.y;
    int tid = ty * 32 + tx;
    int tx0 = blockIdx.x * 32, ty0 = blockIdx.y * 8, b = blockIdx.z;

    if (tid < 96) {
        ws[tid] = (tid < 32) ? co[tid] : (tid < 64) ? bo[tid - 32] : ao[tid - 64];
    }

    int base = (ty + 1) * 34 + tx + 1;
    float res[2];

    #pragma unroll
    for (int ph = 0; ph < 2; ph++) {
        const float* inb = g_bufA + (((uint32_t)(b + ph * 32) * CH) << 16);
        __syncthreads();      // Hs free for (re)write
        for (int t = tid; t < HS1; t += 256) {
            int i   = t / 340;
            int rem = t - i * 340;
            int r   = rem / 34;
            int cc  = rem - r * 34;
            int gy  = (ty0 + r + 255) & 255;
            int gx  = (tx0 + cc + 255) & 255;
            Hs[t] = inb[((uint32_t)i << 16) + (gy << 8) + gx];
        }
        __syncthreads();

        float acc = 0.f;
        #pragma unroll 4
        for (int i = 0; i < 32; i++) {
            const float* h = Hs + i * 340;
            float ctr = h[base];
            float nb  = h[base - 34] + h[base + 34] + h[base - 1]  + h[base + 1];
            float dg  = h[base - 35] + h[base + 35] + h[base - 33] + h[base + 33];
            acc += ws[i] * ctr + ws[32 + i] * nb + ws[64 + i] * dg;
        }
        res[ph] = acc;
    }

    int gy = ty0 + ty, gx = tx0 + tx;
    out[(b << 16) + (gy << 8) + gx] = 0.5f * (res[0] - res[1]);
}

// ---------------- launcher ----------------

extern "C" void kernel_launch(void* const* d_in, const int* in_sizes, int n_in,
                              void* d_out, int out_size)
{
    const float* x      = (const float*)d_in[0];
    const float* ai     = (const float*)d_in[1];
    const float* ao     = (const float*)d_in[2];
    const float* a      = (const float*)d_in[3];
    const float* bi     = (const float*)d_in[4];
    const float* bo     = (const float*)d_in[5];
    const float* b      = (const float*)d_in[6];
    const float* ci     = (const float*)d_in[7];
    const float* co     = (const float*)d_in[8];
    const float* c      = (const float*)d_in[9];
    const float* bias_i = (const float*)d_in[10];
    const float* bias   = (const float*)d_in[11];
    float* out = (float*)d_out;

    cudaFuncSetAttribute(k_mid_mma, cudaFuncAttributeMaxDynamicSharedMemorySize, SMEM_TOTAL);

    dim3 gridM(16, 16, 64);          // both signs in z
    dim3 gridF(8, 32, 64);
    dim3 gridL(8, 32, 32);
    dim3 blkS(32, 8);

    k_wprep<<<8, 256>>>(a, b, c);
    k_first<<<gridF, blkS>>>(x, ci, bi, ai, bias_i);
    int dir = 0;
    for (int k = 0; k < DEPTH; k++) {
        k_mid_mma<<<gridM, 256, SMEM_TOTAL>>>(bias, k, dir);
        dir ^= 1;
    }
    k_last<<<gridL, blkS>>>(co, bo, ao, out);
}